// round 12
// baseline (speedup 1.0000x reference)
#include <cuda_runtime.h>
#include <math.h>

#define C_SIZE 1000
#define NCHUNK 250          // float4 chunks per row
#define ROWS   2            // rows per pipeline stage
#define GRID_BLKS 1184      // 148 SMs x 8 CTAs -> exactly one wave

// Device-global scratch (no allocations allowed).
// INVARIANT: zero at kernel entry; the last-finishing block re-zeroes on the
// way out, so graph replays stay correct.
__device__ float g_conf[C_SIZE];
__device__ int   g_counts[C_SIZE];
__device__ int   g_done;

__global__ __launch_bounds__(128, 8)
void mdca_fused_kernel(const float* __restrict__ logits,
                       const int*   __restrict__ tgt,
                       int B, float* __restrict__ res) {
    __shared__ float sh_ss[ROWS][4];
    __shared__ float sh_se[ROWS][4];
    __shared__ float sh_fin[4];
    __shared__ int   sh_last;

    const int t    = threadIdx.x;
    const int lane = t & 31;
    const int wid  = t >> 5;

    // ---------------- phase 0: target bincount (grid-strided) -------------
    for (int i = blockIdx.x * 128 + t; i < B; i += (int)gridDim.x * 128) {
        int c = tgt[i];
        c = (c < 0) ? 0 : ((c >= C_SIZE) ? C_SIZE - 1 : c);
        atomicAdd(&g_counts[c], 1);
    }

    // ---------------- phase 1: pipelined row processing --------------------
    // Thread t owns float4 chunks t and 128+t in every row. Double-buffered:
    // next group's loads are in flight across the current group's full
    // compute (both barriers included), hiding DRAM latency completely.
    const int   k1    = 128 + t;
    const bool  has1  = (k1 < NCHUNK);
    const float mask1 = has1 ? 1.0f : 0.0f;   // kills exp2(0)=1 on tail threads

    float4 acc0 = make_float4(0.f, 0.f, 0.f, 0.f);
    float4 acc1 = make_float4(0.f, 0.f, 0.f, 0.f);
    const float LOG2E = 1.4426950408889634f;
    const int stride = (int)gridDim.x * ROWS;

    // issue loads for row group starting at r0 into buf
    auto prefetchf = [&](float4 (&buf)[2 * ROWS], int r0) {
        #pragma unroll
        for (int r = 0; r < ROWS; r++) {
            const int row = r0 + r;
            const bool ok = (row < B);
            const float4* __restrict__ rp =
                (const float4*)(logits + (size_t)row * C_SIZE);
            buf[2 * r]     = ok ? rp[t]
                                : make_float4(0.f, 0.f, 0.f, 0.f);
            buf[2 * r + 1] = (ok && has1) ? rp[k1]
                                : make_float4(0.f, 0.f, 0.f, 0.f);
        }
    };

    // full processing of one row group held in buf
    auto processf = [&](float4 (&v)[2 * ROWS], int r0) {
        // ---- sum of squares per row ----
        float ss[ROWS];
        #pragma unroll
        for (int r = 0; r < ROWS; r++) {
            float4 w0 = v[2 * r], w1 = v[2 * r + 1];
            float s;
            s = w0.x * w0.x;
            s = fmaf(w0.y, w0.y, s); s = fmaf(w0.z, w0.z, s);
            s = fmaf(w0.w, w0.w, s);
            s = fmaf(w1.x, w1.x, s); s = fmaf(w1.y, w1.y, s);
            s = fmaf(w1.z, w1.z, s); s = fmaf(w1.w, w1.w, s);
            ss[r] = s;
        }
        #pragma unroll
        for (int o = 16; o > 0; o >>= 1) {
            #pragma unroll
            for (int r = 0; r < ROWS; r++)
                ss[r] += __shfl_xor_sync(0xffffffffu, ss[r], o);
        }
        if (lane == 0) {
            #pragma unroll
            for (int r = 0; r < ROWS; r++) sh_ss[r][wid] = ss[r];
        }
        __syncthreads();                                   // barrier 1

        // ---- exponentials in place + per-row sums ----
        float se[ROWS];
        #pragma unroll
        for (int r = 0; r < ROWS; r++) {
            float s = (sh_ss[r][0] + sh_ss[r][1]) +
                      (sh_ss[r][2] + sh_ss[r][3]);
            const float a = LOG2E * rsqrtf(fmaxf(s, 1e-30f));
            float4 w0 = v[2 * r], w1 = v[2 * r + 1];
            float4 e0, e1;
            e0.x = exp2f(w0.x * a); e0.y = exp2f(w0.y * a);
            e0.z = exp2f(w0.z * a); e0.w = exp2f(w0.w * a);
            e1.x = mask1 * exp2f(w1.x * a); e1.y = mask1 * exp2f(w1.y * a);
            e1.z = mask1 * exp2f(w1.z * a); e1.w = mask1 * exp2f(w1.w * a);
            v[2 * r] = e0; v[2 * r + 1] = e1;
            se[r] = ((e0.x + e0.y) + (e0.z + e0.w)) +
                    ((e1.x + e1.y) + (e1.z + e1.w));
        }
        #pragma unroll
        for (int o = 16; o > 0; o >>= 1) {
            #pragma unroll
            for (int r = 0; r < ROWS; r++)
                se[r] += __shfl_xor_sync(0xffffffffu, se[r], o);
        }
        if (lane == 0) {
            #pragma unroll
            for (int r = 0; r < ROWS; r++) sh_se[r][wid] = se[r];
        }
        __syncthreads();                                   // barrier 2

        // ---- accumulate probabilities ----
        #pragma unroll
        for (int r = 0; r < ROWS; r++) {
            float s = (sh_se[r][0] + sh_se[r][1]) +
                      (sh_se[r][2] + sh_se[r][3]);
            const float rs = (r0 + r < B) ? __fdividef(1.0f, s) : 0.0f;
            float4 e0 = v[2 * r], e1 = v[2 * r + 1];
            acc0.x = fmaf(e0.x, rs, acc0.x); acc0.y = fmaf(e0.y, rs, acc0.y);
            acc0.z = fmaf(e0.z, rs, acc0.z); acc0.w = fmaf(e0.w, rs, acc0.w);
            acc1.x = fmaf(e1.x, rs, acc1.x); acc1.y = fmaf(e1.y, rs, acc1.y);
            acc1.z = fmaf(e1.z, rs, acc1.z); acc1.w = fmaf(e1.w, rs, acc1.w);
        }
    };

    float4 bufA[2 * ROWS], bufB[2 * ROWS];
    int row0 = blockIdx.x * ROWS;
    prefetchf(bufA, row0);

    while (row0 < B) {
        prefetchf(bufB, row0 + stride);      // in flight during process(A)
        processf(bufA, row0);
        row0 += stride;
        if (row0 >= B) break;
        prefetchf(bufA, row0 + stride);      // in flight during process(B)
        processf(bufB, row0);
        row0 += stride;
    }

    // ---------------- phase 2: flush per-block partials --------------------
    {
        const int c0 = 4 * t;
        atomicAdd(&g_conf[c0 + 0], acc0.x);
        atomicAdd(&g_conf[c0 + 1], acc0.y);
        atomicAdd(&g_conf[c0 + 2], acc0.z);
        atomicAdd(&g_conf[c0 + 3], acc0.w);
        if (has1) {
            const int c1 = 4 * k1;
            atomicAdd(&g_conf[c1 + 0], acc1.x);
            atomicAdd(&g_conf[c1 + 1], acc1.y);
            atomicAdd(&g_conf[c1 + 2], acc1.z);
            atomicAdd(&g_conf[c1 + 3], acc1.w);
        }
    }
    __threadfence();
    __syncthreads();

    // ---------------- phase 3: last block computes the scalar --------------
    if (t == 0)
        sh_last = (atomicAdd(&g_done, 1) == (int)gridDim.x - 1) ? 1 : 0;
    __syncthreads();
    if (!sh_last) return;

    // atomicExch reads the final value AND re-zeroes for the next replay.
    float d = 0.0f;
    #pragma unroll
    for (int j = 0; j < 8; j++) {
        int c = t + 128 * j;
        if (c < C_SIZE) {
            float cf = atomicExch(&g_conf[c], 0.0f);
            int   ct = atomicExch(&g_counts[c], 0);
            d += fabsf(cf - (float)ct);
        }
    }
    #pragma unroll
    for (int o = 16; o > 0; o >>= 1)
        d += __shfl_xor_sync(0xffffffffu, d, o);
    if (lane == 0) sh_fin[wid] = d;
    __syncthreads();
    if (t == 0) {
        float tot = (sh_fin[0] + sh_fin[1]) + (sh_fin[2] + sh_fin[3]);
        res[0] = tot / ((float)B * (float)C_SIZE);
        g_done = 0;                       // reset for next graph replay
        __threadfence();
    }
}

// ---------------------------------------------------------------------------
extern "C" void kernel_launch(void* const* d_in, const int* in_sizes, int n_in,
                              void* d_out, int out_size) {
    // Robust input resolution: the [B,1000] fp32 logits tensor is the larger
    // input; the target vector is the smaller one.
    int io = 0, it = 1;
    if (n_in >= 2 && in_sizes[1] > in_sizes[0]) { io = 1; it = 0; }

    const float* logits = (const float*)d_in[io];  // [B, 1000] fp32
    const int*   tgt    = (const int*)d_in[it];    // [B] int32
    float* res = (float*)d_out;

    const int B = in_sizes[it];

    mdca_fused_kernel<<<GRID_BLKS, 128>>>(logits, tgt, B, res);
}